// round 4
// baseline (speedup 1.0000x reference)
#include <cuda_runtime.h>
#include <cstdint>

// ---------------------------------------------------------------------------
// GCN decoder: 4 x (GCNConv [+ReLU] [+upsample x2 folded into next layer])
// Per layer: memset(deg) -> count_deg -> GEMM(hs = rsqrt(deg+1) * x@W, acc=hs)
//            -> scatter(acc[dst] += hs[src], red.v4.f32)
//            -> finalize(out = rsqrt(deg+1)*acc + b [, relu])
// Upsample(repeat rows x2) folded into next GEMM via (row >> shift).
// Self-loop folded into deg+1 and acc seeded with hs.
// ---------------------------------------------------------------------------

#define MAXN 200000
#define MAXF 6400000

__device__ __align__(256) float g_deg[MAXN];
__device__ __align__(256) float g_hs [MAXF];
__device__ __align__(256) float g_acc[MAXF];
__device__ __align__(256) float g_p1 [MAXF];   // ping
__device__ __align__(256) float g_p2 [MAXF];   // pong

// ---------------- degree count ----------------

__global__ void k_count_deg(const int* __restrict__ dst,
                            float* __restrict__ deg, int E) {
    int i = blockIdx.x * blockDim.x + threadIdx.x;
    if (i < E) atomicAdd(&deg[dst[i]], 1.0f);
}

// ---------------- tiled GEMM: hs = rsqrt(deg[row]+1) * (X[row>>shift] @ W) --
// BM x BN tile, BK=16, 8x8 microtile per thread, NT = (BM/8)*(BN/8) threads.

template<int BM, int BN, int NT>
__global__ void k_gemm(const float* __restrict__ X,
                       const float* __restrict__ W,
                       float* __restrict__ hs,
                       float* __restrict__ acc,
                       const float* __restrict__ deg,
                       int M, int K, int F, int shift) {
    constexpr int BK = 16;
    __shared__ float As[BK][BM];   // transposed: As[k][row]
    __shared__ float Bs[BK][BN];

    const int tid = threadIdx.x;
    constexpr int TX = BN / 8;
    const int tx = tid % TX;           // col group
    const int ty = tid / TX;           // row group
    const int row0 = blockIdx.y * BM;
    const int col0 = blockIdx.x * BN;

    float c[8][8] = {};
    float a[8], b[8];

    for (int k0 = 0; k0 < K; k0 += BK) {
        // load A tile: BM*BK/4 float4s, transpose into As[k][row]
        #pragma unroll
        for (int i = tid; i < BM * BK / 4; i += NT) {
            int r  = i / (BK / 4);
            int kc = (i % (BK / 4)) * 4;
            int grow = row0 + r;
            float4 v = make_float4(0.f, 0.f, 0.f, 0.f);
            if (grow < M)
                v = *reinterpret_cast<const float4*>(
                    X + (size_t)(grow >> shift) * K + k0 + kc);
            As[kc + 0][r] = v.x;
            As[kc + 1][r] = v.y;
            As[kc + 2][r] = v.z;
            As[kc + 3][r] = v.w;
        }
        // load B tile
        #pragma unroll
        for (int i = tid; i < BK * BN / 4; i += NT) {
            int r  = i / (BN / 4);
            int cc = (i % (BN / 4)) * 4;
            *reinterpret_cast<float4*>(&Bs[r][cc]) =
                *reinterpret_cast<const float4*>(W + (size_t)(k0 + r) * F + col0 + cc);
        }
        __syncthreads();

        #pragma unroll
        for (int kk = 0; kk < BK; kk++) {
            *reinterpret_cast<float4*>(&a[0]) = *reinterpret_cast<float4*>(&As[kk][ty * 8]);
            *reinterpret_cast<float4*>(&a[4]) = *reinterpret_cast<float4*>(&As[kk][ty * 8 + 4]);
            *reinterpret_cast<float4*>(&b[0]) = *reinterpret_cast<float4*>(&Bs[kk][tx * 8]);
            *reinterpret_cast<float4*>(&b[4]) = *reinterpret_cast<float4*>(&Bs[kk][tx * 8 + 4]);
            #pragma unroll
            for (int i = 0; i < 8; i++)
                #pragma unroll
                for (int j = 0; j < 8; j++)
                    c[i][j] += a[i] * b[j];
        }
        __syncthreads();
    }

    #pragma unroll
    for (int i = 0; i < 8; i++) {
        int row = row0 + ty * 8 + i;
        if (row < M) {
            float dv = rsqrtf(deg[row] + 1.0f);
            size_t off = (size_t)row * F + col0 + tx * 8;
            float4 v0 = make_float4(c[i][0] * dv, c[i][1] * dv, c[i][2] * dv, c[i][3] * dv);
            float4 v1 = make_float4(c[i][4] * dv, c[i][5] * dv, c[i][6] * dv, c[i][7] * dv);
            *reinterpret_cast<float4*>(hs  + off)     = v0;
            *reinterpret_cast<float4*>(hs  + off + 4) = v1;
            *reinterpret_cast<float4*>(acc + off)     = v0;
            *reinterpret_cast<float4*>(acc + off + 4) = v1;
        }
    }
}

// ---------------- small-F GEMM (layer 4: K=64, F=8) -------------------------

__global__ void k_gemm_small(const float* __restrict__ X,
                             const float* __restrict__ W,
                             float* __restrict__ hs,
                             float* __restrict__ acc,
                             const float* __restrict__ deg,
                             int M, int K, int F, int shift) {
    __shared__ float Ws[512];                 // K*F <= 512
    for (int i = threadIdx.x; i < K * F; i += blockDim.x) Ws[i] = W[i];
    __syncthreads();

    int npb = blockDim.x / F;
    int n = blockIdx.x * npb + threadIdx.x / F;
    int f = threadIdx.x % F;
    if (n >= M) return;

    const float* xr = X + (size_t)(n >> shift) * K;
    float s = 0.f;
    #pragma unroll 8
    for (int k = 0; k < K; k++) s += xr[k] * Ws[k * F + f];

    float v = s * rsqrtf(deg[n] + 1.0f);
    hs [(size_t)n * F + f] = v;
    acc[(size_t)n * F + f] = v;
}

// ---------------- edge scatter: acc[dst] += hs[src] (float4 reductions) -----

__device__ __forceinline__ void red_add_v4(float4* addr, float4 v) {
    asm volatile("red.global.add.v4.f32 [%0], {%1, %2, %3, %4};"
                 :: "l"(addr), "f"(v.x), "f"(v.y), "f"(v.z), "f"(v.w)
                 : "memory");
}

__global__ void k_scatter(const int* __restrict__ src,
                          const int* __restrict__ dst,
                          const float* __restrict__ hs,
                          float* __restrict__ acc,
                          long long E, int lf4) {           // lf4 = log2(F/4)
    long long idx = (long long)blockIdx.x * blockDim.x + threadIdx.x;
    long long total = E << lf4;
    if (idx >= total) return;
    long long e = idx >> lf4;
    int c = (int)(idx & ((1 << lf4) - 1));
    int s = src[e];
    int d = dst[e];
    const float4* hs4 = reinterpret_cast<const float4*>(hs);
    float4 v = hs4[((long long)s << lf4) + c];
    red_add_v4(reinterpret_cast<float4*>(acc) + (((long long)d << lf4) + c), v);
}

// ---------------- finalize: out = rsqrt(deg+1)*acc + b [, relu] -------------

__global__ void k_finalize(const float* __restrict__ acc,
                           const float* __restrict__ deg,
                           const float* __restrict__ bias,
                           float* __restrict__ out,
                           long long total4, int lf4, int relu) {
    long long idx = (long long)blockIdx.x * blockDim.x + threadIdx.x;
    if (idx >= total4) return;
    long long n = idx >> lf4;
    int c = (int)(idx & ((1 << lf4) - 1));
    float4 v = reinterpret_cast<const float4*>(acc)[idx];
    float dv = rsqrtf(deg[n] + 1.0f);
    float4 b = reinterpret_cast<const float4*>(bias)[c];
    v.x = v.x * dv + b.x;
    v.y = v.y * dv + b.y;
    v.z = v.z * dv + b.z;
    v.w = v.w * dv + b.w;
    if (relu) {
        v.x = fmaxf(v.x, 0.f); v.y = fmaxf(v.y, 0.f);
        v.z = fmaxf(v.z, 0.f); v.w = fmaxf(v.w, 0.f);
    }
    reinterpret_cast<float4*>(out)[idx] = v;
}

// ---------------- host side -------------------------------------------------

static inline int ilog2(int x) { int l = 0; while ((1 << l) < x) l++; return l; }

static void gcn_layer(const float* x, const int* edges, long long E,
                      const float* W, const float* bias, float* out,
                      int M, int K, int F, int shift, int relu,
                      float* deg, float* hs, float* acc) {
    const int* src = edges;
    const int* dst = edges + E;

    cudaMemsetAsync(deg, 0, (size_t)M * sizeof(float));
    k_count_deg<<<((int)E + 255) / 256, 256>>>(dst, deg, (int)E);

    if (F >= 128) {
        dim3 grid(F / 128, (M + 127) / 128);
        k_gemm<128, 128, 256><<<grid, 256>>>(x, W, hs, acc, deg, M, K, F, shift);
    } else if (F == 64) {
        dim3 grid(1, (M + 127) / 128);
        k_gemm<128, 64, 128><<<grid, 128>>>(x, W, hs, acc, deg, M, K, F, shift);
    } else {
        int npb = 256 / F;
        k_gemm_small<<<(M + npb - 1) / npb, 256>>>(x, W, hs, acc, deg,
                                                   M, K, F, shift);
    }

    int lf4 = ilog2(F / 4);
    long long totE = E << lf4;
    k_scatter<<<(int)((totE + 255) / 256), 256>>>(src, dst, hs, acc, E, lf4);

    long long tot4 = (long long)M << lf4;
    k_finalize<<<(int)((tot4 + 255) / 256), 256>>>(acc, deg, bias, out,
                                                   tot4, lf4, relu);
}

extern "C" void kernel_launch(void* const* d_in, const int* in_sizes, int n_in,
                              void* d_out, int out_size) {
    const float* z   = (const float*)d_in[0];
    const int*   e1  = (const int*)d_in[1];
    const int*   ps2 = (const int*)d_in[2];
    const int*   ps1 = (const int*)d_in[3];
    const int*   ps0 = (const int*)d_in[4];
    const float* W1 = (const float*)d_in[5];
    const float* b1 = (const float*)d_in[6];
    const float* W2 = (const float*)d_in[7];
    const float* b2 = (const float*)d_in[8];
    const float* W3 = (const float*)d_in[9];
    const float* b3 = (const float*)d_in[10];
    const float* W4 = (const float*)d_in[11];
    const float* b4 = (const float*)d_in[12];

    const int h2 = 256, h1 = 128, h0 = 64, oc = 8;
    int N = in_sizes[0] / h2;                   // 25000
    long long E1 = in_sizes[1] / 2;
    long long E2 = in_sizes[2] / 2;
    long long E3 = in_sizes[3] / 2;
    long long E4 = in_sizes[4] / 2;

    float *deg, *hs, *acc, *p1, *p2;
    cudaGetSymbolAddress((void**)&deg, g_deg);
    cudaGetSymbolAddress((void**)&hs,  g_hs);
    cudaGetSymbolAddress((void**)&acc, g_acc);
    cudaGetSymbolAddress((void**)&p1,  g_p1);
    cudaGetSymbolAddress((void**)&p2,  g_p2);

    // L1: [N, 256] -> [N, 256], relu
    gcn_layer(z,  e1,  E1, W1, b1, p1, N,     h2, h2, 0, 1, deg, hs, acc);
    // L2 (upsample folded): [2N, 256] -> [2N, 128], relu
    gcn_layer(p1, ps2, E2, W2, b2, p2, 2 * N, h2, h1, 1, 1, deg, hs, acc);
    // L3: [4N, 128] -> [4N, 64], relu
    gcn_layer(p2, ps1, E3, W3, b3, p1, 4 * N, h1, h0, 1, 1, deg, hs, acc);
    // L4: [8N, 64] -> [8N, 8], no relu, straight to d_out
    gcn_layer(p1, ps0, E4, W4, b4, (float*)d_out, 8 * N, h0, oc, 1, 0,
              deg, hs, acc);
}

// round 5
// speedup vs baseline: 1.1760x; 1.1760x over previous
#include <cuda_runtime.h>
#include <cstdint>

// ---------------------------------------------------------------------------
// GCN decoder: 4 x (GCNConv [+ReLU] [+upsample x2 folded into indexing])
// Per layer:
//   memset(deg)=0; memset(acc)=0
//   count_deg:  deg[dst] += 1
//   rsqrt:      dinv = rsqrt(deg + 1)            (self loop)
//   GEMM:       hraw = X @ W      on RAW rows (pre-upsample, half the rows)
//   scatter:    acc[dst] += dinv[src] * hraw[src>>shift]   (red.v4.f32)
//   finalize:   out = dinv*(acc + dinv*hraw[row>>shift]) + b  [, relu]
// ---------------------------------------------------------------------------

#define MAXN 200000
#define MAXF 6400000

__device__ __align__(256) float g_deg[MAXN];
__device__ __align__(256) float g_hraw[MAXF];
__device__ __align__(256) float g_acc [MAXF];
__device__ __align__(256) float g_p1  [MAXF];   // ping
__device__ __align__(256) float g_p2  [MAXF];   // pong

// ---------------- degree count + dinv ----------------

__global__ void k_count_deg(const int* __restrict__ dst,
                            float* __restrict__ deg, int E) {
    int i = blockIdx.x * blockDim.x + threadIdx.x;
    if (i < E) atomicAdd(&deg[dst[i]], 1.0f);
}

__global__ void k_rsqrt(float* deg, int M) {
    int i = blockIdx.x * blockDim.x + threadIdx.x;
    if (i < M) deg[i] = rsqrtf(deg[i] + 1.0f);
}

// ---------------- tiled GEMM: hraw = X @ W  (proven 64x64, 4x4 microtile) ---
// BM=64, BN=64, BK=16, 256 threads. Mr = raw row count.

__global__ void k_gemm_tiled(const float* __restrict__ X,
                             const float* __restrict__ W,
                             float* __restrict__ hraw,
                             int Mr, int K, int F) {
    __shared__ float As[16][64];   // A transposed: As[k][row]
    __shared__ float Bs[16][64];

    const int tid = threadIdx.x;
    const int tx  = tid & 15;
    const int ty  = tid >> 4;
    const int row0 = blockIdx.y * 64;
    const int col0 = blockIdx.x * 64;

    const int arow = tid >> 2;            // 0..63
    const int ak   = (tid & 3) * 4;       // 0,4,8,12
    const int brow = tid >> 4;            // 0..15
    const int bc   = (tid & 15) * 4;      // 0..60

    float c[4][4] = {};

    for (int k0 = 0; k0 < K; k0 += 16) {
        int grow = row0 + arow;
        float4 av = make_float4(0.f, 0.f, 0.f, 0.f);
        if (grow < Mr) {
            av = *reinterpret_cast<const float4*>(
                X + (size_t)grow * K + k0 + ak);
        }
        As[ak + 0][arow] = av.x;
        As[ak + 1][arow] = av.y;
        As[ak + 2][arow] = av.z;
        As[ak + 3][arow] = av.w;

        float4 bv = *reinterpret_cast<const float4*>(
            W + (size_t)(k0 + brow) * F + col0 + bc);
        *reinterpret_cast<float4*>(&Bs[brow][bc]) = bv;

        __syncthreads();

        #pragma unroll
        for (int kk = 0; kk < 16; kk++) {
            float4 a = *reinterpret_cast<const float4*>(&As[kk][ty * 4]);
            float4 b = *reinterpret_cast<const float4*>(&Bs[kk][tx * 4]);
            c[0][0] += a.x * b.x; c[0][1] += a.x * b.y; c[0][2] += a.x * b.z; c[0][3] += a.x * b.w;
            c[1][0] += a.y * b.x; c[1][1] += a.y * b.y; c[1][2] += a.y * b.z; c[1][3] += a.y * b.w;
            c[2][0] += a.z * b.x; c[2][1] += a.z * b.y; c[2][2] += a.z * b.z; c[2][3] += a.z * b.w;
            c[3][0] += a.w * b.x; c[3][1] += a.w * b.y; c[3][2] += a.w * b.z; c[3][3] += a.w * b.w;
        }
        __syncthreads();
    }

    #pragma unroll
    for (int i = 0; i < 4; i++) {
        int row = row0 + ty * 4 + i;
        if (row < Mr) {
            float4 v = make_float4(c[i][0], c[i][1], c[i][2], c[i][3]);
            *reinterpret_cast<float4*>(hraw + (size_t)row * F + col0 + tx * 4) = v;
        }
    }
}

// ---------------- small-F GEMM (layer 4: K=64, F=8) -------------------------

__global__ void k_gemm_small(const float* __restrict__ X,
                             const float* __restrict__ W,
                             float* __restrict__ hraw,
                             int Mr, int K, int F) {
    __shared__ float Ws[512];                 // K*F <= 512
    for (int i = threadIdx.x; i < K * F; i += blockDim.x) Ws[i] = W[i];
    __syncthreads();

    int npb = blockDim.x / F;
    int n = blockIdx.x * npb + threadIdx.x / F;
    int f = threadIdx.x % F;
    if (n >= Mr) return;

    const float* xr = X + (size_t)n * K;
    float s = 0.f;
    #pragma unroll 8
    for (int k = 0; k < K; k++) s += xr[k] * Ws[k * F + f];

    hraw[(size_t)n * F + f] = s;
}

// ---------------- edge scatter: acc[dst] += dinv[src]*hraw[src>>shift] ------

__device__ __forceinline__ void red_add_v4(float4* addr, float4 v) {
    asm volatile("red.global.add.v4.f32 [%0], {%1, %2, %3, %4};"
                 :: "l"(addr), "f"(v.x), "f"(v.y), "f"(v.z), "f"(v.w)
                 : "memory");
}

__global__ void k_scatter(const int* __restrict__ src,
                          const int* __restrict__ dst,
                          const float* __restrict__ hraw,
                          const float* __restrict__ dinv,
                          float* __restrict__ acc,
                          long long E, int lf4, int shift) {
    long long idx = (long long)blockIdx.x * blockDim.x + threadIdx.x;
    long long total = E << lf4;
    if (idx >= total) return;
    long long e = idx >> lf4;
    int c = (int)(idx & ((1 << lf4) - 1));
    int s = src[e];
    int d = dst[e];
    float sc = dinv[s];
    const float4* h4 = reinterpret_cast<const float4*>(hraw);
    float4 v = h4[((long long)(s >> shift) << lf4) + c];
    v.x *= sc; v.y *= sc; v.z *= sc; v.w *= sc;
    red_add_v4(reinterpret_cast<float4*>(acc) + (((long long)d << lf4) + c), v);
}

// ---------------- finalize: out = dinv*(acc + dinv*hraw) + b [, relu] -------

__global__ void k_finalize(const float* __restrict__ acc,
                           const float* __restrict__ hraw,
                           const float* __restrict__ dinv,
                           const float* __restrict__ bias,
                           float* __restrict__ out,
                           long long total4, int lf4, int shift, int relu) {
    long long idx = (long long)blockIdx.x * blockDim.x + threadIdx.x;
    if (idx >= total4) return;
    long long n = idx >> lf4;
    int c = (int)(idx & ((1 << lf4) - 1));
    float dv = dinv[n];
    float4 a = reinterpret_cast<const float4*>(acc)[idx];
    float4 h = reinterpret_cast<const float4*>(hraw)[(((long long)n >> shift) << lf4) + c];
    float4 b = reinterpret_cast<const float4*>(bias)[c];
    a.x = (a.x + dv * h.x) * dv + b.x;
    a.y = (a.y + dv * h.y) * dv + b.y;
    a.z = (a.z + dv * h.z) * dv + b.z;
    a.w = (a.w + dv * h.w) * dv + b.w;
    if (relu) {
        a.x = fmaxf(a.x, 0.f); a.y = fmaxf(a.y, 0.f);
        a.z = fmaxf(a.z, 0.f); a.w = fmaxf(a.w, 0.f);
    }
    reinterpret_cast<float4*>(out)[idx] = a;
}

// ---------------- host side -------------------------------------------------

static inline int ilog2(int x) { int l = 0; while ((1 << l) < x) l++; return l; }

static void gcn_layer(const float* x, const int* edges, long long E,
                      const float* W, const float* bias, float* out,
                      int M, int K, int F, int shift, int relu,
                      float* deg, float* hraw, float* acc) {
    const int* src = edges;
    const int* dst = edges + E;
    const int Mr = M >> shift;                  // raw (pre-upsample) rows

    cudaMemsetAsync(deg, 0, (size_t)M * sizeof(float));
    cudaMemsetAsync(acc, 0, (size_t)M * F * sizeof(float));
    k_count_deg<<<((int)E + 255) / 256, 256>>>(dst, deg, (int)E);
    k_rsqrt<<<(M + 255) / 256, 256>>>(deg, M);

    if (F >= 64) {
        dim3 grid(F / 64, (Mr + 63) / 64);
        k_gemm_tiled<<<grid, 256>>>(x, W, hraw, Mr, K, F);
    } else {
        int npb = 256 / F;
        k_gemm_small<<<(Mr + npb - 1) / npb, 256>>>(x, W, hraw, Mr, K, F);
    }

    int lf4 = ilog2(F / 4);
    long long totE = E << lf4;
    k_scatter<<<(int)((totE + 255) / 256), 256>>>(src, dst, hraw, deg, acc,
                                                  E, lf4, shift);

    long long tot4 = (long long)M << lf4;
    k_finalize<<<(int)((tot4 + 255) / 256), 256>>>(acc, hraw, deg, bias, out,
                                                   tot4, lf4, shift, relu);
}

extern "C" void kernel_launch(void* const* d_in, const int* in_sizes, int n_in,
                              void* d_out, int out_size) {
    const float* z   = (const float*)d_in[0];
    const int*   e1  = (const int*)d_in[1];
    const int*   ps2 = (const int*)d_in[2];
    const int*   ps1 = (const int*)d_in[3];
    const int*   ps0 = (const int*)d_in[4];
    const float* W1 = (const float*)d_in[5];
    const float* b1 = (const float*)d_in[6];
    const float* W2 = (const float*)d_in[7];
    const float* b2 = (const float*)d_in[8];
    const float* W3 = (const float*)d_in[9];
    const float* b3 = (const float*)d_in[10];
    const float* W4 = (const float*)d_in[11];
    const float* b4 = (const float*)d_in[12];

    const int h2 = 256, h1 = 128, h0 = 64, oc = 8;
    int N = in_sizes[0] / h2;                   // 25000
    long long E1 = in_sizes[1] / 2;
    long long E2 = in_sizes[2] / 2;
    long long E3 = in_sizes[3] / 2;
    long long E4 = in_sizes[4] / 2;

    float *deg, *hraw, *acc, *p1, *p2;
    cudaGetSymbolAddress((void**)&deg,  g_deg);
    cudaGetSymbolAddress((void**)&hraw, g_hraw);
    cudaGetSymbolAddress((void**)&acc,  g_acc);
    cudaGetSymbolAddress((void**)&p1,   g_p1);
    cudaGetSymbolAddress((void**)&p2,   g_p2);

    // L1: [N, 256] -> [N, 256], relu, no upsample
    gcn_layer(z,  e1,  E1, W1, b1, p1, N,     h2, h2, 0, 1, deg, hraw, acc);
    // L2 (upsample x2 folded): [2N] nodes, feats 256 -> 128, relu
    gcn_layer(p1, ps2, E2, W2, b2, p2, 2 * N, h2, h1, 1, 1, deg, hraw, acc);
    // L3: [4N] nodes, 128 -> 64, relu
    gcn_layer(p2, ps1, E3, W3, b3, p1, 4 * N, h1, h0, 1, 1, deg, hraw, acc);
    // L4: [8N] nodes, 64 -> 8, no relu, straight to d_out
    gcn_layer(p1, ps0, E4, W4, b4, (float*)d_out, 8 * N, h0, oc, 1, 0,
              deg, hraw, acc);
}

// round 6
// speedup vs baseline: 1.2099x; 1.0288x over previous
#include <cuda_runtime.h>
#include <cstdint>

// ---------------------------------------------------------------------------
// GCN decoder: 4 x (GCNConv [+ReLU] [+upsample x2 folded into indexing])
// Per layer:
//   memset(deg)=0; memset(acc)=0
//   count_deg:  deg[dst] += 1
//   rsqrt:      dinv = rsqrt(deg + 1)            (self loop)
//   GEMM:       hraw = X @ W      on RAW rows (pre-upsample)
//   scatter:    acc[dst] += dinv[src] * hraw[src>>shift]   (red.v4.f32)
//   finalize:   out = dinv*(acc + dinv*hraw[row>>shift]) + b  [, relu]
// ---------------------------------------------------------------------------

#define MAXN 200000
#define MAXF 6400000

__device__ __align__(256) float g_deg[MAXN];
__device__ __align__(256) float g_hraw[MAXF];
__device__ __align__(256) float g_acc [MAXF];
__device__ __align__(256) float g_p1  [MAXF];   // ping
__device__ __align__(256) float g_p2  [MAXF];   // pong

// ---------------- degree count + dinv ----------------

__global__ void k_count_deg(const int* __restrict__ dst,
                            float* __restrict__ deg, int E) {
    int i = blockIdx.x * blockDim.x + threadIdx.x;
    if (i < E) atomicAdd(&deg[dst[i]], 1.0f);
}

__global__ void k_rsqrt(float* deg, int M) {
    int i = blockIdx.x * blockDim.x + threadIdx.x;
    if (i < M) deg[i] = rsqrtf(deg[i] + 1.0f);
}

// ---------------- tiled GEMM: hraw = X @ W ----------------------------------
// BM=128, BN=64, BK=16, 256 threads, 8x4 microtile per thread.
// 3 LDS.128 per 32 FFMA in the inner loop (vs 2 per 16 in the 4x4 version).

__global__ __launch_bounds__(256) void k_gemm_tiled(
        const float* __restrict__ X,
        const float* __restrict__ W,
        float* __restrict__ hraw,
        int Mr, int K, int F) {
    __shared__ float As[16][128];   // transposed: As[k][row]
    __shared__ float Bs[16][64];

    const int tid = threadIdx.x;
    const int tx  = tid & 15;        // 0..15 -> 4 cols each
    const int ty  = tid >> 4;        // 0..15 -> 8 rows each
    const int row0 = blockIdx.y * 128;
    const int col0 = blockIdx.x * 64;

    // A loader: 512 float4s, 2 per thread
    // B loader: 256 float4s, 1 per thread
    const int brow = tid >> 4;            // 0..15
    const int bc   = (tid & 15) * 4;      // 0..60

    float c[8][4] = {};
    float a[8], b[4];

    for (int k0 = 0; k0 < K; k0 += 16) {
        #pragma unroll
        for (int li = 0; li < 2; li++) {
            int i = tid + li * 256;          // 0..511
            int r  = i >> 2;                 // 0..127
            int kc = (i & 3) * 4;            // 0,4,8,12
            int grow = row0 + r;
            float4 v = make_float4(0.f, 0.f, 0.f, 0.f);
            if (grow < Mr)
                v = *reinterpret_cast<const float4*>(
                    X + (size_t)grow * K + k0 + kc);
            As[kc + 0][r] = v.x;
            As[kc + 1][r] = v.y;
            As[kc + 2][r] = v.z;
            As[kc + 3][r] = v.w;
        }
        *reinterpret_cast<float4*>(&Bs[brow][bc]) =
            *reinterpret_cast<const float4*>(W + (size_t)(k0 + brow) * F + col0 + bc);

        __syncthreads();

        #pragma unroll
        for (int kk = 0; kk < 16; kk++) {
            *reinterpret_cast<float4*>(&a[0]) = *reinterpret_cast<float4*>(&As[kk][ty * 8]);
            *reinterpret_cast<float4*>(&a[4]) = *reinterpret_cast<float4*>(&As[kk][ty * 8 + 4]);
            *reinterpret_cast<float4*>(&b[0]) = *reinterpret_cast<float4*>(&Bs[kk][tx * 4]);
            #pragma unroll
            for (int i = 0; i < 8; i++) {
                c[i][0] += a[i] * b[0];
                c[i][1] += a[i] * b[1];
                c[i][2] += a[i] * b[2];
                c[i][3] += a[i] * b[3];
            }
        }
        __syncthreads();
    }

    #pragma unroll
    for (int i = 0; i < 8; i++) {
        int row = row0 + ty * 8 + i;
        if (row < Mr) {
            float4 v = make_float4(c[i][0], c[i][1], c[i][2], c[i][3]);
            *reinterpret_cast<float4*>(hraw + (size_t)row * F + col0 + tx * 4) = v;
        }
    }
}

// ---------------- small-F GEMM (layer 4: K=64, F=8) -------------------------

__global__ void k_gemm_small(const float* __restrict__ X,
                             const float* __restrict__ W,
                             float* __restrict__ hraw,
                             int Mr, int K, int F) {
    __shared__ float Ws[512];                 // K*F <= 512
    for (int i = threadIdx.x; i < K * F; i += blockDim.x) Ws[i] = W[i];
    __syncthreads();

    int npb = blockDim.x / F;
    int n = blockIdx.x * npb + threadIdx.x / F;
    int f = threadIdx.x % F;
    if (n >= Mr) return;

    const float* xr = X + (size_t)n * K;
    float s = 0.f;
    #pragma unroll 8
    for (int k = 0; k < K; k++) s += xr[k] * Ws[k * F + f];

    hraw[(size_t)n * F + f] = s;
}

// ---------------- edge scatter: acc[dst] += dinv[src]*hraw[src>>shift] ------
// 32-bit index arithmetic throughout (max offset < 2^25).

__device__ __forceinline__ void red_add_v4(float4* addr, float4 v) {
    asm volatile("red.global.add.v4.f32 [%0], {%1, %2, %3, %4};"
                 :: "l"(addr), "f"(v.x), "f"(v.y), "f"(v.z), "f"(v.w)
                 : "memory");
}

__global__ void k_scatter(const int* __restrict__ src,
                          const int* __restrict__ dst,
                          const float* __restrict__ hraw,
                          const float* __restrict__ dinv,
                          float* __restrict__ acc,
                          int total, int lf4, int shift) {
    int idx = blockIdx.x * blockDim.x + threadIdx.x;
    if (idx >= total) return;
    int e = idx >> lf4;
    int c = idx & ((1 << lf4) - 1);
    int s = src[e];
    int d = dst[e];
    float sc = dinv[s];
    const float4* h4 = reinterpret_cast<const float4*>(hraw);
    float4 v = h4[((s >> shift) << lf4) + c];
    v.x *= sc; v.y *= sc; v.z *= sc; v.w *= sc;
    red_add_v4(reinterpret_cast<float4*>(acc) + ((d << lf4) + c), v);
}

// ---------------- finalize: out = dinv*(acc + dinv*hraw) + b [, relu] -------

__global__ void k_finalize(const float* __restrict__ acc,
                           const float* __restrict__ hraw,
                           const float* __restrict__ dinv,
                           const float* __restrict__ bias,
                           float* __restrict__ out,
                           int total4, int lf4, int shift, int relu) {
    int idx = blockIdx.x * blockDim.x + threadIdx.x;
    if (idx >= total4) return;
    int n = idx >> lf4;
    int c = idx & ((1 << lf4) - 1);
    float dv = dinv[n];
    float4 a = reinterpret_cast<const float4*>(acc)[idx];
    float4 h = reinterpret_cast<const float4*>(hraw)[((n >> shift) << lf4) + c];
    float4 b = reinterpret_cast<const float4*>(bias)[c];
    a.x = (a.x + dv * h.x) * dv + b.x;
    a.y = (a.y + dv * h.y) * dv + b.y;
    a.z = (a.z + dv * h.z) * dv + b.z;
    a.w = (a.w + dv * h.w) * dv + b.w;
    if (relu) {
        a.x = fmaxf(a.x, 0.f); a.y = fmaxf(a.y, 0.f);
        a.z = fmaxf(a.z, 0.f); a.w = fmaxf(a.w, 0.f);
    }
    reinterpret_cast<float4*>(out)[idx] = a;
}

// ---------------- host side -------------------------------------------------

static inline int ilog2(int x) { int l = 0; while ((1 << l) < x) l++; return l; }

static void gcn_layer(const float* x, const int* edges, long long E,
                      const float* W, const float* bias, float* out,
                      int M, int K, int F, int shift, int relu,
                      float* deg, float* hraw, float* acc) {
    const int* src = edges;
    const int* dst = edges + E;
    const int Mr = M >> shift;                  // raw (pre-upsample) rows

    cudaMemsetAsync(deg, 0, (size_t)M * sizeof(float));
    cudaMemsetAsync(acc, 0, (size_t)M * F * sizeof(float));
    k_count_deg<<<((int)E + 255) / 256, 256>>>(dst, deg, (int)E);
    k_rsqrt<<<(M + 255) / 256, 256>>>(deg, M);

    if (F >= 64) {
        dim3 grid(F / 64, (Mr + 127) / 128);
        k_gemm_tiled<<<grid, 256>>>(x, W, hraw, Mr, K, F);
    } else {
        int npb = 256 / F;
        k_gemm_small<<<(Mr + npb - 1) / npb, 256>>>(x, W, hraw, Mr, K, F);
    }

    int lf4 = ilog2(F / 4);
    int totE = (int)(E << lf4);
    k_scatter<<<(totE + 255) / 256, 256>>>(src, dst, hraw, deg, acc,
                                           totE, lf4, shift);

    int tot4 = M << lf4;
    k_finalize<<<(tot4 + 255) / 256, 256>>>(acc, hraw, deg, bias, out,
                                            tot4, lf4, shift, relu);
}

extern "C" void kernel_launch(void* const* d_in, const int* in_sizes, int n_in,
                              void* d_out, int out_size) {
    const float* z   = (const float*)d_in[0];
    const int*   e1  = (const int*)d_in[1];
    const int*   ps2 = (const int*)d_in[2];
    const int*   ps1 = (const int*)d_in[3];
    const int*   ps0 = (const int*)d_in[4];
    const float* W1 = (const float*)d_in[5];
    const float* b1 = (const float*)d_in[6];
    const float* W2 = (const float*)d_in[7];
    const float* b2 = (const float*)d_in[8];
    const float* W3 = (const float*)d_in[9];
    const float* b3 = (const float*)d_in[10];
    const float* W4 = (const float*)d_in[11];
    const float* b4 = (const float*)d_in[12];

    const int h2 = 256, h1 = 128, h0 = 64, oc = 8;
    int N = in_sizes[0] / h2;                   // 25000
    long long E1 = in_sizes[1] / 2;
    long long E2 = in_sizes[2] / 2;
    long long E3 = in_sizes[3] / 2;
    long long E4 = in_sizes[4] / 2;

    float *deg, *hraw, *acc, *p1, *p2;
    cudaGetSymbolAddress((void**)&deg,  g_deg);
    cudaGetSymbolAddress((void**)&hraw, g_hraw);
    cudaGetSymbolAddress((void**)&acc,  g_acc);
    cudaGetSymbolAddress((void**)&p1,   g_p1);
    cudaGetSymbolAddress((void**)&p2,   g_p2);

    // L1: [N, 256] -> [N, 256], relu, no upsample
    gcn_layer(z,  e1,  E1, W1, b1, p1, N,     h2, h2, 0, 1, deg, hraw, acc);
    // L2 (upsample x2 folded): [2N] nodes, feats 256 -> 128, relu
    gcn_layer(p1, ps2, E2, W2, b2, p2, 2 * N, h2, h1, 1, 1, deg, hraw, acc);
    // L3: [4N] nodes, 128 -> 64, relu
    gcn_layer(p2, ps1, E3, W3, b3, p1, 4 * N, h1, h0, 1, 1, deg, hraw, acc);
    // L4: [8N] nodes, 64 -> 8, no relu, straight to d_out
    gcn_layer(p1, ps0, E4, W4, b4, (float*)d_out, 8 * N, h0, oc, 1, 0,
              deg, hraw, acc);
}